// round 3
// baseline (speedup 1.0000x reference)
#include <cuda_runtime.h>
#include <math.h>

#define B_Q   256
#define N_T   100000
#define D_F   768
#define D_V4  192            // D_F/4
#define K_TOP 5
#define TWO_D 1536
#define S_MAX 256
#define NSEG  4
#define IDX_INVALID 0x7fffffff

// ---------------- scratch (static device globals; no runtime alloc) ----------
__device__ int   g_cnt[S_MAX];
__device__ int   g_off[S_MAX + 1];
__device__ int   g_cur[S_MAX];
__device__ int   g_list[N_T];
__device__ float g_pwv[B_Q * NSEG * K_TOP];
__device__ int   g_pwi[B_Q * NSEG * K_TOP];
__device__ int   g_hasmatch[B_Q];
__device__ float g_combined[B_Q * TWO_D];
__device__ float g_h[B_Q * D_F];
__device__ int   g_is64;

// ---------------- int64/int32 speaker-id autodetect --------------------------
// jax without x64 silently stores ids as int32; with x64 they are int64.
// If int64 (values in [0,256)), every odd 32-bit word is zero. If int32, odd
// words are random speaker ids (all-zero across 50k odd slots impossible).
__global__ void detect_i64_kernel(const int* __restrict__ spk_words, int count_elems) {
    __shared__ int any;
    if (threadIdx.x == 0) any = 0;
    __syncthreads();
    int local = 0;
    for (int i = 1 + 2 * (int)threadIdx.x; i < count_elems; i += 2 * (int)blockDim.x)
        local |= spk_words[i];
    if (local) atomicOr(&any, 1);
    __syncthreads();
    if (threadIdx.x == 0) g_is64 = (any == 0) ? 1 : 0;
}

__device__ __forceinline__ int get_id(const int* __restrict__ p, int i) {
    return g_is64 ? p[2 * i] : p[i];
}

// ---------------- speaker CSR build ------------------------------------------
__global__ void zero_cnt_kernel() { g_cnt[threadIdx.x] = 0; }

__global__ void hist_kernel(const int* __restrict__ spk) {
    int i = blockIdx.x * blockDim.x + threadIdx.x;
    if (i < N_T) atomicAdd(&g_cnt[get_id(spk, i) & (S_MAX - 1)], 1);
}

__global__ void scan_kernel() {
    int t = threadIdx.x;
    if (t == 0) {
        int acc = 0;
        for (int i = 0; i < S_MAX; i++) { g_off[i] = acc; acc += g_cnt[i]; }
        g_off[S_MAX] = acc;
    }
    __syncthreads();
    g_cur[t] = g_off[t];
}

__global__ void scatter_kernel(const int* __restrict__ spk) {
    int i = blockIdx.x * blockDim.x + threadIdx.x;
    if (i < N_T) {
        int s = get_id(spk, i) & (S_MAX - 1);
        int pos = atomicAdd(&g_cur[s], 1);
        g_list[pos] = i;
    }
}

// ---------------- per-(query, segment) candidate search ----------------------
// grid (B_Q, NSEG), 256 threads. Warp w of segment s handles candidates
// start + s*8 + w + 32*t. Exact fp32 dot + row norm via float4 loads; per-warp
// top-5 with (value desc, index asc) comparator; block merge to per-seg top-5.
__global__ void __launch_bounds__(256)
search_kernel(const float* __restrict__ Q, const float* __restrict__ T,
              const int* __restrict__ tgt) {
    const int b = blockIdx.x, seg = blockIdx.y;
    const int tid = threadIdx.x, lane = tid & 31, wid = tid >> 5;

    __shared__ float4 sq4[D_V4];
    __shared__ float red[256];
    __shared__ float swv[8][K_TOP];
    __shared__ int   swi[8][K_TOP];
    __shared__ float s_invq;

    // load query into smem + block-reduce its squared norm
    float part = 0.f;
    for (int k = tid; k < D_V4; k += 256) {
        float4 v = ((const float4*)(Q + (size_t)b * D_F))[k];
        sq4[k] = v;
        part += v.x * v.x + v.y * v.y + v.z * v.z + v.w * v.w;
    }
    red[tid] = part;
    __syncthreads();
    for (int s = 128; s > 0; s >>= 1) {
        if (tid < s) red[tid] += red[tid + s];
        __syncthreads();
    }
    if (tid == 0) s_invq = 1.0f / fmaxf(sqrtf(red[0]), 1e-8f);
    __syncthreads();

    const int tg = get_id(tgt, b);
    const int start = g_off[tg], end = g_off[tg + 1];
    const float invq = s_invq;

    float lv[K_TOP]; int li[K_TOP];
    #pragma unroll
    for (int j = 0; j < K_TOP; j++) { lv[j] = -3.4e38f; li[j] = IDX_INVALID; }

    for (int c = start + seg * 8 + wid; c < end; c += NSEG * 8) {
        const int idx = g_list[c];
        const float4* __restrict__ r = (const float4*)(T + (size_t)idx * D_F);
        float dot = 0.f, nn = 0.f;
        #pragma unroll
        for (int k = 0; k < 6; k++) {
            float4 rv = __ldg(&r[lane + 32 * k]);
            float4 qv = sq4[lane + 32 * k];
            dot += qv.x * rv.x + qv.y * rv.y + qv.z * rv.z + qv.w * rv.w;
            nn  += rv.x * rv.x + rv.y * rv.y + rv.z * rv.z + rv.w * rv.w;
        }
        #pragma unroll
        for (int o = 16; o; o >>= 1) {
            dot += __shfl_xor_sync(0xffffffffu, dot, o);
            nn  += __shfl_xor_sync(0xffffffffu, nn,  o);
        }
        if (lane == 0) {
            float v = dot * invq * (1.0f / fmaxf(sqrtf(nn), 1e-8f));
            if (v > lv[K_TOP - 1] || (v == lv[K_TOP - 1] && idx < li[K_TOP - 1])) {
                lv[K_TOP - 1] = v; li[K_TOP - 1] = idx;
                #pragma unroll
                for (int j = K_TOP - 1; j > 0; j--) {
                    if (lv[j] > lv[j - 1] || (lv[j] == lv[j - 1] && li[j] < li[j - 1])) {
                        float tv = lv[j]; lv[j] = lv[j - 1]; lv[j - 1] = tv;
                        int   ti = li[j]; li[j] = li[j - 1]; li[j - 1] = ti;
                    }
                }
            }
        }
    }

    if (lane == 0) {
        #pragma unroll
        for (int j = 0; j < K_TOP; j++) { swv[wid][j] = lv[j]; swi[wid][j] = li[j]; }
    }
    __syncthreads();

    if (tid == 0) {
        // merge 8 warps' lists (each sorted) into segment top-5
        float mv[8 * K_TOP]; int mi[8 * K_TOP];
        for (int s = 0; s < 8 * K_TOP; s++) { mv[s] = swv[s / K_TOP][s % K_TOP]; mi[s] = swi[s / K_TOP][s % K_TOP]; }
        float* ov = g_pwv + (b * NSEG + seg) * K_TOP;
        int*   oi = g_pwi + (b * NSEG + seg) * K_TOP;
        for (int r = 0; r < K_TOP; r++) {
            float bv = -3.4e38f; int bi = IDX_INVALID; int bs = -1;
            for (int s = 0; s < 8 * K_TOP; s++) {
                if (mi[s] == IDX_INVALID) continue;
                if (mv[s] > bv || (mv[s] == bv && mi[s] < bi)) { bv = mv[s]; bi = mi[s]; bs = s; }
            }
            ov[r] = bv; oi[r] = bi;
            if (bs >= 0) { mi[bs] = IDX_INVALID; mv[bs] = -3.4e38f; }
        }
    }
}

// ---------------- merge segments + gather mean + concat ----------------------
__global__ void __launch_bounds__(256)
merge_gather_kernel(const float* __restrict__ content, const float* __restrict__ T,
                    const int* __restrict__ spk, const int* __restrict__ tgt) {
    const int b = blockIdx.x;
    const int tid = threadIdx.x;
    __shared__ int s_idx[K_TOP];

    if (tid == 0) {
        float mv[NSEG * K_TOP]; int mi[NSEG * K_TOP];
        for (int s = 0; s < NSEG * K_TOP; s++) {
            mv[s] = g_pwv[b * NSEG * K_TOP + s];
            mi[s] = g_pwi[b * NSEG * K_TOP + s];
        }
        const int tg = get_id(tgt, b);
        int fill_n = 0;
        for (int r = 0; r < K_TOP; r++) {
            float bv = -3.4e38f; int bi = IDX_INVALID; int bs = -1;
            for (int s = 0; s < NSEG * K_TOP; s++) {
                if (mi[s] == IDX_INVALID) continue;
                if (mv[s] > bv || (mv[s] == bv && mi[s] < bi)) { bv = mv[s]; bi = mi[s]; bs = s; }
            }
            if (bs >= 0) {
                s_idx[r] = bi;
                mi[bs] = IDX_INVALID; mv[bs] = -3.4e38f;
            } else {
                // reference: leftover -1e30 slots tie-break to smallest index
                // whose speaker != target
                while (fill_n < N_T && get_id(spk, fill_n) == tg) fill_n++;
                s_idx[r] = (fill_n < N_T) ? fill_n : 0;
                if (fill_n < N_T) fill_n++;
            }
        }
        g_hasmatch[b] = (g_off[tg + 1] > g_off[tg]) ? 1 : 0;
    }
    __syncthreads();

    const float* r0 = T + (size_t)s_idx[0] * D_F;
    const float* r1 = T + (size_t)s_idx[1] * D_F;
    const float* r2 = T + (size_t)s_idx[2] * D_F;
    const float* r3 = T + (size_t)s_idx[3] * D_F;
    const float* r4 = T + (size_t)s_idx[4] * D_F;
    for (int d = tid; d < D_F; d += 256) {
        float rmean = 0.2f * (r0[d] + r1[d] + r2[d] + r3[d] + r4[d]);
        g_combined[b * TWO_D + d]       = content[(size_t)b * D_F + d];
        g_combined[b * TWO_D + D_F + d] = rmean;
    }
}

// ---------------- MLP layer 1: h = silu(combined @ W1 + b1) ------------------
#define BROWS 8
__global__ void __launch_bounds__(256)
mlp1_kernel(const float* __restrict__ W1, const float* __restrict__ b1) {
    const int b0 = blockIdx.x * BROWS;
    const int d  = blockIdx.y * 256 + threadIdx.x;
    __shared__ float s[BROWS][TWO_D];
    for (int r = 0; r < BROWS; r++)
        for (int k = threadIdx.x; k < TWO_D; k += 256)
            s[r][k] = g_combined[(b0 + r) * TWO_D + k];
    __syncthreads();

    float acc[BROWS];
    float bb = b1[d];
    #pragma unroll
    for (int r = 0; r < BROWS; r++) acc[r] = bb;

    #pragma unroll 4
    for (int k = 0; k < TWO_D; k++) {
        float w = W1[(size_t)k * D_F + d];
        #pragma unroll
        for (int r = 0; r < BROWS; r++) acc[r] += s[r][k] * w;
    }
    #pragma unroll
    for (int r = 0; r < BROWS; r++) {
        float x = acc[r];
        g_h[(b0 + r) * D_F + d] = x / (1.0f + __expf(-x));   // silu
    }
}

// ---------------- MLP layer 2 + passthrough ----------------------------------
__global__ void __launch_bounds__(256)
mlp2_kernel(const float* __restrict__ W2, const float* __restrict__ b2,
            const float* __restrict__ content, float* __restrict__ out) {
    const int b0 = blockIdx.x * BROWS;
    const int d  = blockIdx.y * 256 + threadIdx.x;
    __shared__ float s[BROWS][D_F];
    for (int r = 0; r < BROWS; r++)
        for (int k = threadIdx.x; k < D_F; k += 256)
            s[r][k] = g_h[(b0 + r) * D_F + k];
    __syncthreads();

    float acc[BROWS];
    float bb = b2[d];
    #pragma unroll
    for (int r = 0; r < BROWS; r++) acc[r] = bb;

    #pragma unroll 4
    for (int k = 0; k < D_F; k++) {
        float w = W2[(size_t)k * D_F + d];
        #pragma unroll
        for (int r = 0; r < BROWS; r++) acc[r] += s[r][k] * w;
    }
    #pragma unroll
    for (int r = 0; r < BROWS; r++) {
        float v = g_hasmatch[b0 + r] ? acc[r]
                                     : content[(size_t)(b0 + r) * D_F + d];
        out[(size_t)(b0 + r) * D_F + d] = v;
    }
}

// ---------------- launcher ----------------------------------------------------
extern "C" void kernel_launch(void* const* d_in, const int* in_sizes, int n_in,
                              void* d_out, int out_size) {
    const float* content = (const float*)d_in[0];
    const int*   tgt     = (const int*)  d_in[1];
    const float* train   = (const float*)d_in[2];
    const int*   spk     = (const int*)  d_in[3];
    const float* W1      = (const float*)d_in[4];
    const float* b1      = (const float*)d_in[5];
    const float* W2      = (const float*)d_in[6];
    const float* b2      = (const float*)d_in[7];
    float* out = (float*)d_out;

    const int nb = (N_T + 255) / 256;

    detect_i64_kernel<<<1, 256>>>(spk, N_T);
    zero_cnt_kernel<<<1, S_MAX>>>();
    hist_kernel<<<nb, 256>>>(spk);
    scan_kernel<<<1, S_MAX>>>();
    scatter_kernel<<<nb, 256>>>(spk);

    dim3 sg(B_Q, NSEG);
    search_kernel<<<sg, 256>>>(content, train, tgt);
    merge_gather_kernel<<<B_Q, 256>>>(content, train, spk, tgt);

    dim3 mg(B_Q / BROWS, 3);
    mlp1_kernel<<<mg, 256>>>(W1, b1);
    mlp2_kernel<<<mg, 256>>>(W2, b2, content, out);
}

// round 9
// speedup vs baseline: 1.0965x; 1.0965x over previous
#include <cuda_runtime.h>
#include <math.h>

#define B_Q   256
#define N_T   100000
#define D_F   768
#define D_V4  192            // D_F/4
#define K_TOP 5
#define TWO_D 1536
#define S_MAX 256
#define IDX_INVALID 0x7fffffff
#define NEG_INF (-3.4e38f)

// ---------------- scratch (static device globals; no runtime alloc) ----------
__device__ int   g_cnt[S_MAX];
__device__ int   g_off[S_MAX + 1];
__device__ int   g_cur[S_MAX];
__device__ int   g_list[N_T];
__device__ int   g_hasmatch[B_Q];
__device__ float g_combined[B_Q * TWO_D];
__device__ float g_h[B_Q * D_F];
__device__ int   g_any;      // any odd 32-bit word nonzero -> ids are int32

// ---------------- setup: zero counters + detect flag --------------------------
__global__ void setup_kernel() {
    g_cnt[threadIdx.x] = 0;
    if (threadIdx.x == 0) g_any = 0;
}

// ---------------- int64/int32 speaker-id autodetect (grid-parallel) ----------
// jax without x64 silently stores ids as int32; with x64 they are int64.
// int64 values in [0,256) -> every odd 32-bit word zero. int32 -> odd words
// are random ids (all-zero across 50k odd slots impossible).
__global__ void detect_kernel(const int* __restrict__ w, int n) {
    int stride = gridDim.x * blockDim.x;
    int local = 0;
    for (int j = 1 + 2 * (blockIdx.x * blockDim.x + threadIdx.x); j < n; j += 2 * stride)
        local |= w[j];
    if (local) g_any = 1;    // benign race: all writers store 1
}

__device__ __forceinline__ int id_at(const int* __restrict__ p, int i, int is64) {
    return (is64 ? p[2 * i] : p[i]) & (S_MAX - 1);
}

// ---------------- histogram (smem-aggregated) ---------------------------------
__global__ void __launch_bounds__(512)
hist_kernel(const int* __restrict__ spk) {
    __shared__ int h[S_MAX];
    const int t = threadIdx.x;
    for (int i = t; i < S_MAX; i += 512) h[i] = 0;
    __syncthreads();
    const int is64 = (g_any == 0);
    for (int i = blockIdx.x * 512 + t; i < N_T; i += gridDim.x * 512)
        atomicAdd(&h[id_at(spk, i, is64)], 1);
    __syncthreads();
    for (int i = t; i < S_MAX; i += 512)
        if (h[i]) atomicAdd(&g_cnt[i], h[i]);
}

// ---------------- parallel inclusive scan (256 elements) ----------------------
__global__ void scan_kernel() {
    __shared__ int s[S_MAX];
    const int t = threadIdx.x;
    const int c = g_cnt[t];
    s[t] = c;
    __syncthreads();
    #pragma unroll
    for (int o = 1; o < S_MAX; o <<= 1) {
        int v = (t >= o) ? s[t - o] : 0;
        __syncthreads();
        s[t] += v;
        __syncthreads();
    }
    g_off[t + 1] = s[t];
    if (t == 0) g_off[0] = 0;
    g_cur[t] = s[t] - c;     // exclusive prefix
}

// ---------------- scatter ------------------------------------------------------
__global__ void __launch_bounds__(512)
scatter_kernel(const int* __restrict__ spk) {
    const int is64 = (g_any == 0);
    for (int i = blockIdx.x * 512 + threadIdx.x; i < N_T; i += gridDim.x * 512) {
        int pos = atomicAdd(&g_cur[id_at(spk, i, is64)], 1);
        g_list[pos] = i;
    }
}

// ---------------- top-5 insert (value desc, index asc) ------------------------
__device__ __forceinline__ void top5_insert(float (&lv)[K_TOP], int (&li)[K_TOP],
                                            float v, int idx) {
    if (v > lv[K_TOP - 1] || (v == lv[K_TOP - 1] && idx < li[K_TOP - 1])) {
        lv[K_TOP - 1] = v; li[K_TOP - 1] = idx;
        #pragma unroll
        for (int j = K_TOP - 1; j > 0; j--) {
            if (lv[j] > lv[j - 1] || (lv[j] == lv[j - 1] && li[j] < li[j - 1])) {
                float tv = lv[j]; lv[j] = lv[j - 1]; lv[j - 1] = tv;
                int   ti = li[j]; li[j] = li[j - 1]; li[j - 1] = ti;
            }
        }
    }
}

// ---------------- fused search + top-5 + gather + concat -----------------------
// One 512-thread block (16 warps) per query. Warp-per-candidate with ILP2:
// warp w handles candidates (start+w, start+w+16), stride 32 — coalesced
// lane-strided float4 row reads (4 wavefronts per LDG.128, not 32). Query row
// lives in 6 float4 registers per lane. Per-warp top-5 at lane 0, then a
// 5-round block argmax (value desc, index asc) selects the exact global top-5.
__global__ void __launch_bounds__(512)
search_gather_kernel(const float* __restrict__ Q, const float* __restrict__ T,
                     const int* __restrict__ spk, const int* __restrict__ tgt,
                     const float* __restrict__ content) {
    const int b = blockIdx.x;
    const int tid = threadIdx.x, lane = tid & 31, wid = tid >> 5;   // 16 warps

    __shared__ float wv[16];
    __shared__ int   wi[16];
    __shared__ int   s_bi;
    __shared__ int   s_idx[K_TOP];

    // ---- query row in registers (lane-strided) + warp-redundant norm ----
    const float4* __restrict__ q4 = (const float4*)(Q + (size_t)b * D_F);
    float4 q[6];
    float qq = 0.f;
    #pragma unroll
    for (int k = 0; k < 6; k++) {
        q[k] = __ldg(&q4[lane + 32 * k]);
        qq += q[k].x * q[k].x + q[k].y * q[k].y + q[k].z * q[k].z + q[k].w * q[k].w;
    }
    #pragma unroll
    for (int o = 16; o; o >>= 1) qq += __shfl_xor_sync(0xffffffffu, qq, o);
    const float invq = 1.0f / fmaxf(sqrtf(qq), 1e-8f);

    const int is64 = (g_any == 0);
    const int tg = (is64 ? tgt[2 * b] : tgt[b]) & (S_MAX - 1);
    const int start = g_off[tg], end = g_off[tg + 1];

    // ---- warp-per-candidate (ILP2, pipelined index loads) ----
    float lv[K_TOP]; int li[K_TOP];
    #pragma unroll
    for (int j = 0; j < K_TOP; j++) { lv[j] = NEG_INF; li[j] = IDX_INVALID; }

    int c = start + wid;
    int idxA_n = (c      < end) ? __ldg(&g_list[c])      : 0;
    int idxB_n = (c + 16 < end) ? __ldg(&g_list[c + 16]) : 0;
    for (; c < end; c += 32) {
        const int cB = c + 16;
        const bool hB = (cB < end);
        const int idxA = idxA_n;
        const int idxB = hB ? idxB_n : idxA;
        // prefetch next iteration's indices before the row loop
        if (c + 32 < end) idxA_n = __ldg(&g_list[c + 32]);
        if (c + 48 < end) idxB_n = __ldg(&g_list[c + 48]);

        const float4* __restrict__ rA = (const float4*)(T + (size_t)idxA * D_F);
        const float4* __restrict__ rB = (const float4*)(T + (size_t)idxB * D_F);

        float dA = 0.f, nA = 0.f, dB = 0.f, nB = 0.f;
        #pragma unroll
        for (int k = 0; k < 6; k++) {
            float4 a = __ldg(&rA[lane + 32 * k]);
            float4 x = __ldg(&rB[lane + 32 * k]);
            dA += q[k].x * a.x + q[k].y * a.y + q[k].z * a.z + q[k].w * a.w;
            nA += a.x * a.x + a.y * a.y + a.z * a.z + a.w * a.w;
            dB += q[k].x * x.x + q[k].y * x.y + q[k].z * x.z + q[k].w * x.w;
            nB += x.x * x.x + x.y * x.y + x.z * x.z + x.w * x.w;
        }
        #pragma unroll
        for (int o = 16; o; o >>= 1) {
            dA += __shfl_xor_sync(0xffffffffu, dA, o);
            nA += __shfl_xor_sync(0xffffffffu, nA, o);
            dB += __shfl_xor_sync(0xffffffffu, dB, o);
            nB += __shfl_xor_sync(0xffffffffu, nB, o);
        }
        if (lane == 0) {
            top5_insert(lv, li, dA * invq * (1.0f / fmaxf(sqrtf(nA), 1e-8f)), idxA);
            if (hB)
                top5_insert(lv, li, dB * invq * (1.0f / fmaxf(sqrtf(nB), 1e-8f)), idxB);
        }
    }
    // lanes != 0 carry empty (NEG_INF) lists into the generic block merge below

    // ---- 5-round block argmax merge ----
    int cur = 0;   // cursor into my sorted local list
    for (int r = 0; r < K_TOP; r++) {
        float cv = (cur < K_TOP) ? lv[cur] : NEG_INF;
        int   ci = (cur < K_TOP) ? li[cur] : IDX_INVALID;
        #pragma unroll
        for (int o = 16; o; o >>= 1) {
            float ov = __shfl_xor_sync(0xffffffffu, cv, o);
            int   oi = __shfl_xor_sync(0xffffffffu, ci, o);
            if (ov > cv || (ov == cv && oi < ci)) { cv = ov; ci = oi; }
        }
        if (lane == 0) { wv[wid] = cv; wi[wid] = ci; }
        __syncthreads();
        if (wid == 0) {
            float bv = (lane < 16) ? wv[lane] : NEG_INF;
            int   bi = (lane < 16) ? wi[lane] : IDX_INVALID;
            #pragma unroll
            for (int o = 8; o; o >>= 1) {
                float ov = __shfl_xor_sync(0xffffffffu, bv, o);
                int   oi = __shfl_xor_sync(0xffffffffu, bi, o);
                if (ov > bv || (ov == bv && oi < bi)) { bv = ov; bi = oi; }
            }
            if (lane == 0) s_bi = bi;
        }
        __syncthreads();
        if (cur < K_TOP && s_bi != IDX_INVALID && li[cur] == s_bi) cur++;  // winner retires
        if (tid == 0) s_idx[r] = s_bi;
        __syncthreads();
    }

    // ---- under-full fill (reference: -1e30 ties -> smallest non-target index)
    if (tid == 0) {
        int fill_n = 0;
        for (int r = 0; r < K_TOP; r++) {
            if (s_idx[r] == IDX_INVALID) {
                while (fill_n < N_T && id_at(spk, fill_n, is64) == tg) fill_n++;
                s_idx[r] = (fill_n < N_T) ? fill_n : 0;
                if (fill_n < N_T) fill_n++;
            }
        }
        g_hasmatch[b] = (end > start) ? 1 : 0;
    }
    __syncthreads();

    // ---- gather mean of top-5 + concat ----
    const float* r0 = T + (size_t)s_idx[0] * D_F;
    const float* r1 = T + (size_t)s_idx[1] * D_F;
    const float* r2 = T + (size_t)s_idx[2] * D_F;
    const float* r3 = T + (size_t)s_idx[3] * D_F;
    const float* r4 = T + (size_t)s_idx[4] * D_F;
    for (int d = tid; d < D_F; d += 512) {
        float rmean = 0.2f * (r0[d] + r1[d] + r2[d] + r3[d] + r4[d]);
        g_combined[b * TWO_D + d]       = content[(size_t)b * D_F + d];
        g_combined[b * TWO_D + D_F + d] = rmean;
    }
}

// ---------------- MLP layer 1: h = silu(combined @ W1 + b1) --------------------
#define BROWS 4
__global__ void __launch_bounds__(256)
mlp1_kernel(const float* __restrict__ W1, const float* __restrict__ b1) {
    const int b0 = blockIdx.x * BROWS;
    const int d  = blockIdx.y * 256 + threadIdx.x;
    __shared__ float s[BROWS][TWO_D];
    for (int r = 0; r < BROWS; r++)
        for (int k = threadIdx.x; k < TWO_D; k += 256)
            s[r][k] = g_combined[(b0 + r) * TWO_D + k];
    __syncthreads();

    float acc[BROWS];
    float bb = __ldg(&b1[d]);
    #pragma unroll
    for (int r = 0; r < BROWS; r++) acc[r] = bb;

    #pragma unroll 8
    for (int k = 0; k < TWO_D; k++) {
        float w = __ldg(&W1[(size_t)k * D_F + d]);
        #pragma unroll
        for (int r = 0; r < BROWS; r++) acc[r] += s[r][k] * w;
    }
    #pragma unroll
    for (int r = 0; r < BROWS; r++) {
        float x = acc[r];
        g_h[(b0 + r) * D_F + d] = x / (1.0f + __expf(-x));   // silu
    }
}

// ---------------- MLP layer 2 + passthrough ------------------------------------
__global__ void __launch_bounds__(256)
mlp2_kernel(const float* __restrict__ W2, const float* __restrict__ b2,
            const float* __restrict__ content, float* __restrict__ out) {
    const int b0 = blockIdx.x * BROWS;
    const int d  = blockIdx.y * 256 + threadIdx.x;
    __shared__ float s[BROWS][D_F];
    for (int r = 0; r < BROWS; r++)
        for (int k = threadIdx.x; k < D_F; k += 256)
            s[r][k] = g_h[(b0 + r) * D_F + k];
    __syncthreads();

    float acc[BROWS];
    float bb = __ldg(&b2[d]);
    #pragma unroll
    for (int r = 0; r < BROWS; r++) acc[r] = bb;

    #pragma unroll 8
    for (int k = 0; k < D_F; k++) {
        float w = __ldg(&W2[(size_t)k * D_F + d]);
        #pragma unroll
        for (int r = 0; r < BROWS; r++) acc[r] += s[r][k] * w;
    }
    #pragma unroll
    for (int r = 0; r < BROWS; r++) {
        float v = g_hasmatch[b0 + r] ? acc[r]
                                     : content[(size_t)(b0 + r) * D_F + d];
        out[(size_t)(b0 + r) * D_F + d] = v;
    }
}

// ---------------- launcher ------------------------------------------------------
extern "C" void kernel_launch(void* const* d_in, const int* in_sizes, int n_in,
                              void* d_out, int out_size) {
    const float* content = (const float*)d_in[0];
    const int*   tgt     = (const int*)  d_in[1];
    const float* train   = (const float*)d_in[2];
    const int*   spk     = (const int*)  d_in[3];
    const float* W1      = (const float*)d_in[4];
    const float* b1      = (const float*)d_in[5];
    const float* W2      = (const float*)d_in[6];
    const float* b2      = (const float*)d_in[7];
    float* out = (float*)d_out;

    setup_kernel<<<1, S_MAX>>>();          // launch 0
    detect_kernel<<<64, 256>>>(spk, N_T);  // launch 1
    hist_kernel<<<128, 512>>>(spk);        // launch 2
    scan_kernel<<<1, S_MAX>>>();           // launch 3
    scatter_kernel<<<128, 512>>>(spk);     // launch 4

    // launch 5 == ncu capture slot (-s 5 -c 1): the kernel we need data on
    search_gather_kernel<<<B_Q, 512>>>(content, train, spk, tgt, content);

    dim3 mg(B_Q / BROWS, 3);
    mlp1_kernel<<<mg, 256>>>(W1, b1);
    mlp2_kernel<<<mg, 256>>>(W2, b2, content, out);
}